// round 2
// baseline (speedup 1.0000x reference)
#include <cuda_runtime.h>
#include <math.h>

// ChfLoss: B=8, H=W=64, P=2*CHF_STEP=60.
// loss = (CHF_TIK / B) * sum_b || CHF(dnn_b - gt_b) ||_2
// Separable trig: angle[p,q,(i,j)] = r_q*x_i + r_p*y_j, x_axis == y_axis.

#define NB      8
#define HWD     64
#define PP      60
#define PTILES  15     // 60 / 4 p-rows per block

// Scratch (no device allocation allowed; __device__ globals are the sanctioned path)
__device__ float g_CT[HWD * PP];          // [i][q] : cos(r_q * x_i), transposed
__device__ float g_ST[HWD * PP];          // [i][q] : sin(r_q * x_i)
__device__ float g_part[NB * PTILES];     // per-block partial sum of squares

// ---------------------------------------------------------------------------
// Kernel 1: trig tables. One sincos per thread, evaluated in double on the
// fp32-rounded argument (matches reference's fl(r_q * x_i); immune to fast-math).
// ---------------------------------------------------------------------------
__global__ void chf_trig_kernel() {
    int idx = blockIdx.x * blockDim.x + threadIdx.x;   // 0 .. 3839
    if (idx >= PP * HWD) return;
    int q = idx / HWD;
    int i = idx - q * HWD;
    float r = (float)(q - 30) * 0.1f;                  // CHF_TIK grid, fp32 like ref
    float x = (float)(4 + 8 * i);                      // linspace(4, 508, 64), exact
    double a = (double)(r * x);                        // fp32 product rounding, then exact trig
    g_CT[i * PP + q] = (float)cos(a);
    g_ST[i * PP + q] = (float)sin(a);
}

// ---------------------------------------------------------------------------
// Kernel 2: per (batch, 4-row p-tile) block.
//   stage 1: A_c[p,i] = sum_j C[p,j]*D[j,i] ; A_s likewise   (1 output pair / thread)
//   stage 2: real/imag over all q for the 4 p rows, accumulate real^2+imag^2
// Shared: D 4096 + CT 3840 + ST 3840 + Ac 256 + As 256 = 12288 floats = 48KB exactly.
// ---------------------------------------------------------------------------
__global__ __launch_bounds__(256) void chf_main_kernel(const float* __restrict__ dnn,
                                                       const float* __restrict__ gt) {
    extern __shared__ float sm[];
    float* sD  = sm;               // [j*64 + i]
    float* sCT = sm + 4096;        // [i*60 + q]  (also read as [j*60 + p])
    float* sST = sm + 7936;
    float* sAc = sm + 11776;       // [i*4 + pl]
    float* sAs = sm + 12032;       // [i*4 + pl]   (sAc reused as reduce buf at end)

    const int blk = blockIdx.x;
    const int b   = blk / PTILES;
    const int pt  = blk - b * PTILES;
    const int p0  = pt * 4;
    const int t   = threadIdx.x;

    const float* db = dnn + b * 4096;
    const float* gb = gt  + b * 4096;
    for (int idx = t; idx < 4096; idx += 256)
        sD[idx] = db[idx] - gb[idx];
    for (int idx = t; idx < HWD * PP; idx += 256) {
        sCT[idx] = g_CT[idx];
        sST[idx] = g_ST[idx];
    }
    __syncthreads();

    // ---- stage 1: thread t -> (pl = t>>6, i = t&63), p = p0+pl ----
    {
        const int pl = t >> 6;
        const int i  = t & 63;
        const int p  = p0 + pl;
        float ac = 0.f, as = 0.f;
        #pragma unroll 16
        for (int j = 0; j < 64; j++) {
            float d = sD[j * 64 + i];       // conflict-free (i = lane)
            float c = sCT[j * PP + p];      // broadcast (p uniform per warp)
            float s = sST[j * PP + p];
            ac = fmaf(c, d, ac);
            as = fmaf(s, d, as);
        }
        sAc[i * 4 + pl] = ac;
        sAs[i * 4 + pl] = as;
    }
    __syncthreads();

    // ---- stage 2: threads 0..239 -> (pl = t/60, q = t%60) ----
    float re = 0.f, im = 0.f;
    if (t < 240) {
        const int pl = t / 60;
        const int q  = t - pl * 60;
        #pragma unroll 16
        for (int i = 0; i < 64; i++) {
            float ac = sAc[i * 4 + pl];     // broadcast
            float as = sAs[i * 4 + pl];
            float c  = sCT[i * PP + q];     // consecutive q -> conflict-free
            float s  = sST[i * PP + q];
            re = fmaf(ac, c, re);
            re = fmaf(-as, s, re);
            im = fmaf(as, c, im);
            im = fmaf(ac, s, im);
        }
    }
    float v = fmaf(re, re, im * im);

    // ---- block reduce sum of squares ----
    #pragma unroll
    for (int off = 16; off > 0; off >>= 1)
        v += __shfl_down_sync(0xFFFFFFFFu, v, off);

    __syncthreads();                     // all sAc reads done; safe to reuse
    if ((t & 31) == 0) sAc[t >> 5] = v;  // 8 warp partials
    __syncthreads();
    if (t < 8) {
        v = sAc[t];
        #pragma unroll
        for (int off = 4; off > 0; off >>= 1)
            v += __shfl_down_sync(0x000000FFu, v, off);
        if (t == 0) g_part[blk] = v;
    }
}

// ---------------------------------------------------------------------------
// Kernel 3: deterministic finalize. thread b<8 sums its 15 partials, sqrt,
// warp-reduce sum, scale by CHF_TIK / B.
// ---------------------------------------------------------------------------
__global__ void chf_final_kernel(float* __restrict__ out) {
    int t = threadIdx.x;       // 32 threads
    float v = 0.f;
    if (t < NB) {
        float s = 0.f;
        #pragma unroll
        for (int k = 0; k < PTILES; k++)
            s += g_part[t * PTILES + k];
        v = sqrtf(s);
    }
    #pragma unroll
    for (int off = 16; off > 0; off >>= 1)
        v += __shfl_down_sync(0xFFFFFFFFu, v, off);
    if (t == 0) out[0] = v * 0.1f / 8.0f;
}

// ---------------------------------------------------------------------------
extern "C" void kernel_launch(void* const* d_in, const int* in_sizes, int n_in,
                              void* d_out, int out_size) {
    (void)in_sizes; (void)n_in; (void)out_size;
    const float* dnn = (const float*)d_in[0];
    const float* gt  = (const float*)d_in[1];
    float* out = (float*)d_out;

    chf_trig_kernel<<<15, 256>>>();
    chf_main_kernel<<<NB * PTILES, 256, 12288 * sizeof(float)>>>(dnn, gt);
    chf_final_kernel<<<1, 32>>>(out);
}

// round 4
// speedup vs baseline: 1.2182x; 1.2182x over previous
#include <cuda_runtime.h>
#include <math.h>

// ChfLoss: B=8, H=W=64, P=60. loss = (0.1/B) * sum_b ||CHF(dnn_b - gt_b)||_2
// Separable trig: angle[p,q,(i,j)] = r_q*x_i + r_p*y_j, x_axis == y_axis.

#define NB      8
#define HWD     64
#define PP      60
#define PTILES  15                  // 60 / 4 p-rows per block
#define NBLK    (NB * PTILES)       // 120

// __device__ globals = sanctioned scratch (no allocation allowed)
__device__ float    g_CS[HWD * PP * 2];   // interleaved [(i*60+q)*2] = cos, +1 = sin
__device__ float    g_part[NBLK];         // per-block partial sum of squares
__device__ unsigned g_count = 0;          // last-block-done counter (self-resetting)

// ---------------------------------------------------------------------------
// Kernel 1: trig tables. Reference forms angle = fl(r_q * x_i) in fp32 then
// cos/sin. We take that exact fp32 product, range-reduce in fp64 (3 ops,
// error ~6e-15 since |k| <= 243), then sincosf on |ar| <= pi — accurate even
// under fast_math.
// ---------------------------------------------------------------------------
__global__ void chf_trig_kernel() {
    int idx = blockIdx.x * blockDim.x + threadIdx.x;   // 0 .. 3839
    if (idx >= PP * HWD) return;
    int q = idx / HWD;
    int i = idx - q * HWD;
    float r  = (float)(q - 30) * 0.1f;                 // fp32 grid, matches ref
    float x  = (float)(4 + 8 * i);                     // linspace(4,508,64), exact
    float rx = r * x;                                  // ref's fp32 rounding
    double a  = (double)rx;
    double k  = rint(a * 0.15915494309189535);         // 1/(2*pi)
    double ar = fma(-k, 6.283185307179586, a);         // |ar| <= pi
    float arf = (float)ar;
    float s, c;
    sincosf(arf, &s, &c);
    g_CS[(i * PP + q) * 2 + 0] = c;
    g_CS[(i * PP + q) * 2 + 1] = s;
}

// ---------------------------------------------------------------------------
// Kernel 2 (fused main + finalize): block = (batch b, 4-row p-tile).
//   stage 1: A_c[p,i] = sum_j C[p,j]*D[j,i] ; A_s likewise
//   stage 2: re/im over all q for the 4 p rows; accumulate re^2+im^2
//   epilogue: block reduce -> g_part; last block sums deterministically,
//             per-batch sqrt, writes loss.
// Shared: D 4096 + CS 7680 + A 512 = 12288 floats = 48KB dynamic exactly.
// NO static __shared__ anywhere (would push past the 48KB default limit).
// ---------------------------------------------------------------------------
__global__ __launch_bounds__(256) void chf_main_kernel(const float* __restrict__ dnn,
                                                       const float* __restrict__ gt,
                                                       float* __restrict__ out) {
    extern __shared__ float sm[];
    float*  sD   = sm;                               // [j*64 + i]
    float2* sCS  = (float2*)(sm + 4096);             // [i*60 + q] (also [j*60 + p])
    float2* sA   = (float2*)(sm + 4096 + 7680);      // [i*4 + pl]

    const int blk = blockIdx.x;
    const int b   = blk / PTILES;
    const int pt  = blk - b * PTILES;
    const int p0  = pt * 4;
    const int t   = threadIdx.x;

    const float*  db  = dnn + b * 4096;
    const float*  gb  = gt  + b * 4096;
    const float2* gCS = (const float2*)g_CS;
    for (int idx = t; idx < 4096; idx += 256)
        sD[idx] = db[idx] - gb[idx];
    for (int idx = t; idx < HWD * PP; idx += 256)
        sCS[idx] = gCS[idx];
    __syncthreads();

    // ---- stage 1: thread t -> (pl = t>>6, i = t&63), p = p0+pl ----
    {
        const int pl = t >> 6;
        const int i  = t & 63;
        const int p  = p0 + pl;
        float ac = 0.f, as = 0.f;
        #pragma unroll 16
        for (int j = 0; j < 64; j++) {
            float  d  = sD[j * 64 + i];      // conflict-free (i = lane)
            float2 cs = sCS[j * PP + p];     // 64-bit broadcast (p uniform per warp)
            ac = fmaf(cs.x, d, ac);
            as = fmaf(cs.y, d, as);
        }
        sA[i * 4 + pl] = make_float2(ac, as);
    }
    __syncthreads();

    // ---- stage 2: threads 0..239 -> (pl = t/60, q = t%60) ----
    float re = 0.f, im = 0.f;
    if (t < 240) {
        const int pl = t / 60;
        const int q  = t - pl * 60;
        #pragma unroll 16
        for (int i = 0; i < 64; i++) {
            float2 a  = sA[i * 4 + pl];      // 64-bit broadcast
            float2 cs = sCS[i * PP + q];     // consecutive q -> conflict-free
            re = fmaf(a.x, cs.x, re);
            re = fmaf(-a.y, cs.y, re);
            im = fmaf(a.y, cs.x, im);
            im = fmaf(a.x, cs.y, im);
        }
    }
    float v = fmaf(re, re, im * im);

    // ---- block reduce sum of squares ----
    #pragma unroll
    for (int off = 16; off > 0; off >>= 1)
        v += __shfl_down_sync(0xFFFFFFFFu, v, off);

    __syncthreads();                       // stage-2 smem reads done; reuse sD
    if ((t & 31) == 0) sD[t >> 5] = v;     // 8 warp partials
    __syncthreads();
    if (t == 0) {
        float s = 0.f;
        #pragma unroll
        for (int w = 0; w < 8; w++) s += sD[w];
        g_part[blk] = s;
        __threadfence();                   // release g_part before counter bump
        unsigned c = atomicAdd(&g_count, 1u);
        bool last = (c == NBLK - 1);
        if (last) g_count = 0;             // reset for next graph replay
        sD[8] = last ? 1.f : 0.f;          // flag via dynamic smem (no static shared)
    }
    __syncthreads();

    // ---- last block: deterministic finalize ----
    if (sD[8] != 0.f) {
        __threadfence();                   // acquire: all g_part visible
        float w = 0.f;
        if (t < NB) {
            float s = 0.f;
            #pragma unroll
            for (int k = 0; k < PTILES; k++)
                s += g_part[t * PTILES + k];   // fixed order -> deterministic
            w = sqrtf(s);
        }
        if (t < 32) {
            #pragma unroll
            for (int off = 16; off > 0; off >>= 1)
                w += __shfl_down_sync(0xFFFFFFFFu, w, off);
            if (t == 0) out[0] = w * 0.1f / 8.0f;
        }
    }
}

// ---------------------------------------------------------------------------
extern "C" void kernel_launch(void* const* d_in, const int* in_sizes, int n_in,
                              void* d_out, int out_size) {
    (void)in_sizes; (void)n_in; (void)out_size;
    const float* dnn = (const float*)d_in[0];
    const float* gt  = (const float*)d_in[1];
    float* out = (float*)d_out;

    chf_trig_kernel<<<30, 128>>>();
    chf_main_kernel<<<NBLK, 256, 12288 * sizeof(float)>>>(dnn, gt, out);
}

// round 5
// speedup vs baseline: 1.9107x; 1.5685x over previous
#include <cuda_runtime.h>
#include <math.h>

// ChfLoss: B=8, H=W=64, P=60. loss = (0.1/B) * sum_b ||CHF(dnn_b - gt_b)||_2
// Separable trig: angle[p,q,(i,j)] = r_q*x_i + r_p*y_j, x_axis == y_axis.
// Single fused kernel: 120 co-resident blocks; each produces 32 trig-table
// entries, spin-waits on a counter, then does the two-stage contraction.

#define NB      8
#define HWD     64
#define PP      60
#define PTILES  15                  // 60 / 4 p-rows per block
#define NBLK    (NB * PTILES)       // 120

// __device__ globals = sanctioned scratch (no allocation allowed)
__device__ float    g_CS[HWD * PP * 2];   // interleaved [(i*60+q)*2] = cos, +1 = sin
__device__ float    g_part[NBLK];         // per-block partial sum of squares
__device__ unsigned g_done  = 0;          // trig-table-ready counter (self-resetting)
__device__ unsigned g_count = 0;          // epilogue counter (self-resetting)

// Shared: D 4096 + CS 7680 + A 512 = 12288 floats = 48KB dynamic exactly.
// NO static __shared__ anywhere (would exceed the 48KB default limit).
__global__ __launch_bounds__(256) void chf_fused_kernel(const float* __restrict__ dnn,
                                                        const float* __restrict__ gt,
                                                        float* __restrict__ out) {
    extern __shared__ float sm[];
    float*  sD  = sm;                               // [j*64 + i]
    float2* sCS = (float2*)(sm + 4096);             // [i*60 + q] (also [j*60 + p])
    float2* sA  = (float2*)(sm + 4096 + 7680);      // [i*4 + pl]

    const int blk = blockIdx.x;
    const int b   = blk / PTILES;
    const int pt  = blk - b * PTILES;
    const int p0  = pt * 4;
    const int t   = threadIdx.x;

    // ---- phase B (warp 0 first): produce this block's 32 trig entries ----
    // Reference forms angle = fl(r_q * x_i) in fp32, then cos/sin. We take that
    // exact fp32 product, range-reduce in fp64 (3 ops, err ~6e-15, |k|<=243),
    // then sincosf on |ar| <= pi — accurate even under fast_math.
    if (t < 32) {
        int e = blk * 32 + t;                        // 0 .. 3839
        int q = e >> 6;                              // e / 64
        int i = e & 63;
        float r  = (float)(q - 30) * 0.1f;           // fp32 grid, matches ref
        float x  = (float)(4 + 8 * i);               // linspace(4,508,64), exact
        float rx = r * x;                            // ref's fp32 rounding
        double a  = (double)rx;
        double k  = rint(a * 0.15915494309189535);   // 1/(2*pi)
        double ar = fma(-k, 6.283185307179586, a);   // |ar| <= pi
        float s, c;
        sincosf((float)ar, &s, &c);
        ((float2*)g_CS)[i * PP + q] = make_float2(c, s);
        __threadfence();                             // release writes
        if (t == 0) atomicAdd(&g_done, 1u);
    }

    // ---- phase A: D = dnn - gt into shared (no table needed) ----
    {
        const float4* d4 = (const float4*)(dnn + b * 4096);
        const float4* g4 = (const float4*)(gt  + b * 4096);
        float4* sD4 = (float4*)sD;
        #pragma unroll
        for (int k = 0; k < 4; k++) {
            int idx = t + k * 256;                   // 1024 float4 total
            float4 a = d4[idx], g = g4[idx];
            sD4[idx] = make_float4(a.x - g.x, a.y - g.y, a.z - g.z, a.w - g.w);
        }
    }

    // ---- phase C: wait for full table (all 120 blocks co-resident) ----
    if (t == 0) {
        while (*((volatile unsigned*)&g_done) < NBLK) __nanosleep(32);
        __threadfence();                             // acquire
    }
    __syncthreads();

    // ---- phase D: stage table into shared ----
    {
        const float2* gCS = (const float2*)g_CS;
        #pragma unroll
        for (int k = 0; k < 15; k++)
            sCS[t + k * 256] = gCS[t + k * 256];
    }
    __syncthreads();

    // ---- stage 1: thread t -> (pl = t>>6, i = t&63), p = p0+pl ----
    {
        const int pl = t >> 6;
        const int i  = t & 63;
        const int p  = p0 + pl;
        float ac = 0.f, as = 0.f;
        #pragma unroll 16
        for (int j = 0; j < 64; j++) {
            float  d  = sD[j * 64 + i];      // conflict-free (i = lane)
            float2 cs = sCS[j * PP + p];     // 64-bit broadcast (p uniform per warp)
            ac = fmaf(cs.x, d, ac);
            as = fmaf(cs.y, d, as);
        }
        sA[i * 4 + pl] = make_float2(ac, as);
    }
    __syncthreads();

    // ---- stage 2: threads 0..239 -> (pl = t/60, q = t%60) ----
    // Split accumulator chains: dependent depth 64 instead of 128.
    float re1 = 0.f, re2 = 0.f, im1 = 0.f, im2 = 0.f;
    if (t < 240) {
        const int pl = t / 60;
        const int q  = t - pl * 60;
        #pragma unroll 16
        for (int i = 0; i < 64; i++) {
            float2 a  = sA[i * 4 + pl];      // 64-bit broadcast
            float2 cs = sCS[i * PP + q];     // consecutive q -> conflict-free
            re1 = fmaf(a.x, cs.x, re1);
            re2 = fmaf(a.y, cs.y, re2);
            im1 = fmaf(a.y, cs.x, im1);
            im2 = fmaf(a.x, cs.y, im2);
        }
    }
    float re = re1 - re2;
    float im = im1 + im2;
    float v  = fmaf(re, re, im * im);

    // ---- block reduce sum of squares ----
    #pragma unroll
    for (int off = 16; off > 0; off >>= 1)
        v += __shfl_down_sync(0xFFFFFFFFu, v, off);

    __syncthreads();                       // stage-2 smem reads done; reuse sD
    if ((t & 31) == 0) sD[t >> 5] = v;     // 8 warp partials
    __syncthreads();
    if (t == 0) {
        float s = 0.f;
        #pragma unroll
        for (int w = 0; w < 8; w++) s += sD[w];
        g_part[blk] = s;
        __threadfence();                   // release g_part before counter bump
        unsigned c = atomicAdd(&g_count, 1u);
        bool last = (c == NBLK - 1);
        if (last) {                        // every block has passed the spin by now
            g_count = 0;                   // reset for next graph replay
            g_done  = 0;
        }
        sD[8] = last ? 1.f : 0.f;          // flag via dynamic smem (no static shared)
    }
    __syncthreads();

    // ---- last block: deterministic finalize ----
    if (sD[8] != 0.f) {
        __threadfence();                   // acquire: all g_part visible
        float w = 0.f;
        if (t < NB) {
            float s = 0.f;
            #pragma unroll
            for (int k = 0; k < PTILES; k++)
                s += g_part[t * PTILES + k];   // fixed order -> deterministic
            w = sqrtf(s);
        }
        if (t < 32) {
            #pragma unroll
            for (int off = 16; off > 0; off >>= 1)
                w += __shfl_down_sync(0xFFFFFFFFu, w, off);
            if (t == 0) out[0] = w * 0.1f / 8.0f;
        }
    }
}

// ---------------------------------------------------------------------------
extern "C" void kernel_launch(void* const* d_in, const int* in_sizes, int n_in,
                              void* d_out, int out_size) {
    (void)in_sizes; (void)n_in; (void)out_size;
    const float* dnn = (const float*)d_in[0];
    const float* gt  = (const float*)d_in[1];
    float* out = (float*)d_out;

    chf_fused_kernel<<<NBLK, 256, 12288 * sizeof(float)>>>(dnn, gt, out);
}